// round 2
// baseline (speedup 1.0000x reference)
#include <cuda_runtime.h>
#include <math.h>

namespace {
constexpr int CL = 18, X = 200, Y = 200, Z = 16;
constexpr int Xd = 100, Yd = 100, Zd = 16;
constexpr int NV = Xd * Yd * Zd;      // 160000
constexpr int NCOLS = Xd * Yd;        // 10000
constexpr int NVF = X * Y * Z;        // 640000
}

// ------------------------- device-global scratch ---------------------------
__device__ float d_fast[4 * 64 * NV];
__device__ float d_z[64 * NV];
__device__ float d_zw[64 * NV];
__device__ float d_fadv[64 * NV];
__device__ float d_dX[64 * NV];
__device__ float d_k1[64 * NV];
__device__ float d_h[32 * NV];
__device__ float d_c[32 * NV];
__device__ float d_tinv[3][12];
__device__ float d_dtau[3];
__device__ float d_gsum[8];
__device__ float d_gss[8];
__device__ float d_gmr[16];
__device__ float d_wfe[486 * 64];
__device__ float d_wse[486 * 64];
__device__ float d_wbody[3][864 * 32];
__device__ float d_wdec[1728 * 18];
__device__ float d_wctrl[65 * 64];
__device__ float d_wgin[128 * 32];
__device__ float d_wgout[32 * 64];

// ------------------------- weight repack: [C][J] -> [J][C] -----------------
__global__ void k_repack(const float* __restrict__ in, float* __restrict__ outp, int C, int J) {
    int i = blockIdx.x * 256 + threadIdx.x;
    if (i < C * J) { int c = i / J, j = i - c * J; outp[j * C + c] = in[i]; }
}

// --------- per-step transforms: tinv = inv(pose[k]) @ pose[k+1], dtau ------
__global__ void k_transforms(const float* __restrict__ pose, const int* __restrict__ ts) {
    if (threadIdx.x != 0 || blockIdx.x != 0) return;
    for (int k = 0; k < 3; k++) {
        float A[4][4], Iv[4][4];
        for (int r = 0; r < 4; r++)
            for (int c = 0; c < 4; c++) {
                A[r][c] = pose[k * 16 + r * 4 + c];
                Iv[r][c] = (r == c) ? 1.f : 0.f;
            }
        for (int c = 0; c < 4; c++) {
            int piv = c;
            for (int r = c + 1; r < 4; r++)
                if (fabsf(A[r][c]) > fabsf(A[piv][c])) piv = r;
            if (piv != c)
                for (int j = 0; j < 4; j++) {
                    float t = A[c][j]; A[c][j] = A[piv][j]; A[piv][j] = t;
                    t = Iv[c][j]; Iv[c][j] = Iv[piv][j]; Iv[piv][j] = t;
                }
            float dinv = 1.f / A[c][c];
            for (int j = 0; j < 4; j++) { A[c][j] *= dinv; Iv[c][j] *= dinv; }
            for (int r = 0; r < 4; r++) {
                if (r == c) continue;
                float f = A[r][c];
                for (int j = 0; j < 4; j++) { A[r][j] -= f * A[c][j]; Iv[r][j] -= f * Iv[c][j]; }
            }
        }
        const float* B = pose + (k + 1) * 16;
        for (int r = 0; r < 3; r++)
            for (int c = 0; c < 4; c++) {
                float s = 0.f;
                for (int j = 0; j < 4; j++) s += Iv[r][j] * B[j * 4 + c];
                d_tinv[k][r * 4 + c] = s;
            }
        d_dtau[k] = (float)(ts[k + 1] - ts[k]) * 1e-6f;
    }
}

// -------- encoder conv 18->64, 3x3x3, stride (2,2,1), pad 1, ReLU ----------
__global__ void __launch_bounds__(128) k_enc(const float* __restrict__ in,
                                             const float* __restrict__ wt,
                                             const float* __restrict__ b,
                                             float* __restrict__ out) {
    __shared__ __align__(16) float patch[2 * CL * 9 * 20];
    int tid = threadIdx.x;
    int p0 = blockIdx.x * 2;
    for (int i = tid; i < 2 * CL * 9 * 18; i += 128) {
        int lc = i / (CL * 9 * 18);
        int r = i - lc * (CL * 9 * 18);
        int ci = r / (9 * 18);
        int r2 = r - ci * (9 * 18);
        int dd = r2 / 18;
        int ziz = r2 - dd * 18;
        int p = p0 + lc;
        int x = p / Yd, y = p - x * Yd;
        int ix = 2 * x - 1 + dd / 3, iy = 2 * y - 1 + dd % 3, iz = ziz - 1;
        float v = 0.f;
        if ((unsigned)ix < (unsigned)X && (unsigned)iy < (unsigned)Y && (unsigned)iz < (unsigned)Z)
            v = __ldg(&in[((ci * X + ix) * Y + iy) * Z + iz]);
        patch[((lc * CL + ci) * 9 + dd) * 20 + ziz] = v;
    }
    __syncthreads();
    int lc = tid >> 6, c = tid & 63;
    int p = p0 + lc;
    float bb = __ldg(&b[c]);
    float acc[16];
#pragma unroll
    for (int z = 0; z < 16; z++) acc[z] = bb;
    const float* pb = patch + lc * CL * 9 * 20;
#pragma unroll 1
    for (int ci = 0; ci < CL; ci++) {
#pragma unroll
        for (int dd = 0; dd < 9; dd++) {
            const float* col = pb + (ci * 9 + dd) * 20;
            float v[18];
            const float4* c4 = reinterpret_cast<const float4*>(col);
#pragma unroll
            for (int q = 0; q < 4; q++) {
                float4 t = c4[q];
                v[4 * q] = t.x; v[4 * q + 1] = t.y; v[4 * q + 2] = t.z; v[4 * q + 3] = t.w;
            }
            v[16] = col[16]; v[17] = col[17];
            const float* wp = wt + (ci * 27 + dd * 3) * 64 + c;
#pragma unroll
            for (int kz = 0; kz < 3; kz++) {
                float ww = __ldg(&wp[kz * 64]);
#pragma unroll
                for (int z = 0; z < 16; z++) acc[z] = fmaf(v[z + kz], ww, acc[z]);
            }
        }
    }
    float* op = out + c * NV + p * 16;
#pragma unroll
    for (int z = 0; z < 16; z++) op[z] = fmaxf(acc[z], 0.f);
}

__global__ void k_sub(float* __restrict__ z, const float* __restrict__ f0, int n) {
    int i = blockIdx.x * 256 + threadIdx.x;
    if (i < n) z[i] -= f0[i];
}

// ---------------- trilinear backward warp of z and fast[k] -----------------
__global__ void k_warp(const float* __restrict__ zin, const float* __restrict__ fin,
                       float* __restrict__ zw, float* __restrict__ fadv, int step) {
    int v = blockIdx.x * 256 + threadIdx.x;
    int p = v >> 4, z = v & 15;
    int x = p / Yd, y = p - x * Yd;
    float wxw = -40.f + (x + 0.5f) * 0.8f;
    float wyw = -40.f + (y + 0.5f) * 0.8f;
    float wzw = -1.f + (z + 0.5f) * 0.4f;
    const float* M = d_tinv[step];
    float px = M[0] * wxw + M[1] * wyw + M[2] * wzw + M[3];
    float py = M[4] * wxw + M[5] * wyw + M[6] * wzw + M[7];
    float pz = M[8] * wxw + M[9] * wyw + M[10] * wzw + M[11];
    float gxf = (px + 40.f) / 0.8f - 0.5f;
    float gyf = (py + 40.f) / 0.8f - 0.5f;
    float gzf = (pz + 1.f) / 0.4f - 0.5f;
    gxf = fminf(fmaxf(gxf, 0.f), 99.f);
    gyf = fminf(fmaxf(gyf, 0.f), 99.f);
    gzf = fminf(fmaxf(gzf, 0.f), 15.f);
    float fx0 = floorf(gxf), fy0 = floorf(gyf), fz0 = floorf(gzf);
    int x0 = (int)fx0, y0 = (int)fy0, z0 = (int)fz0;
    int x1 = min(x0 + 1, 99), y1 = min(y0 + 1, 99), z1 = min(z0 + 1, 15);
    float fx = gxf - fx0, fy = gyf - fy0, fz = gzf - fz0;
    float cx0 = 1.f - fx, cy0 = 1.f - fy, cz0 = 1.f - fz;
    float w000 = cx0 * cy0 * cz0, w100 = fx * cy0 * cz0, w010 = cx0 * fy * cz0, w110 = fx * fy * cz0;
    float w001 = cx0 * cy0 * fz, w101 = fx * cy0 * fz, w011 = cx0 * fy * fz, w111 = fx * fy * fz;
    int o00 = (x0 * Yd + y0) * Zd, o01 = (x0 * Yd + y1) * Zd;
    int o10 = (x1 * Yd + y0) * Zd, o11 = (x1 * Yd + y1) * Zd;
#pragma unroll 4
    for (int c = 0; c < 64; c++) {
        const float* a = zin + c * NV;
        float r = __ldg(a + o00 + z0) * w000 + __ldg(a + o10 + z0) * w100
                + __ldg(a + o01 + z0) * w010 + __ldg(a + o11 + z0) * w110
                + __ldg(a + o00 + z1) * w001 + __ldg(a + o10 + z1) * w101
                + __ldg(a + o01 + z1) * w011 + __ldg(a + o11 + z1) * w111;
        zw[c * NV + v] = r;
        const float* f = fin + c * NV;
        float r2 = __ldg(f + o00 + z0) * w000 + __ldg(f + o10 + z0) * w100
                 + __ldg(f + o01 + z0) * w010 + __ldg(f + o11 + z0) * w110
                 + __ldg(f + o00 + z1) * w001 + __ldg(f + o10 + z1) * w101
                 + __ldg(f + o01 + z1) * w011 + __ldg(f + o11 + z1) * w111;
        fadv[c * NV + v] = r2;
    }
}

// ----------------- ctrl: dX = W(64x65)[f_t - f_adv; dtau] + b --------------
__global__ void __launch_bounds__(256) k_ctrl(const float* __restrict__ ft, const float* __restrict__ fadv,
                                              const float* __restrict__ wt, const float* __restrict__ b,
                                              float* __restrict__ dX, int step) {
    __shared__ float w[65 * 64 + 64];
    int tid = threadIdx.x;
    for (int i = tid; i < 65 * 64; i += 256) w[i] = wt[i];
    for (int i = tid; i < 64; i += 256) w[65 * 64 + i] = b[i];
    __syncthreads();
    int v = blockIdx.x * 256 + tid;
    float dt = d_dtau[step];
    float acc[64];
#pragma unroll
    for (int co = 0; co < 64; co++) acc[co] = w[65 * 64 + co];
#pragma unroll 1
    for (int ci = 0; ci < 65; ci++) {
        float val = (ci < 64) ? (ft[ci * NV + v] - fadv[ci * NV + v]) : dt;
#pragma unroll
        for (int co = 0; co < 64; co++) acc[co] = fmaf(w[ci * 64 + co], val, acc[co]);
    }
#pragma unroll
    for (int co = 0; co < 64; co++) dX[co * NV + v] = acc[co];
}

// ----------------- g_in: h = relu(W(32x128)[A(+A2); B] + b) ----------------
__global__ void __launch_bounds__(256) k_gin(const float* __restrict__ A, const float* __restrict__ A2,
                                             const float* __restrict__ B, const float* __restrict__ wt,
                                             const float* __restrict__ b, float* __restrict__ h) {
    __shared__ float w[128 * 32 + 32];
    int tid = threadIdx.x;
    for (int i = tid; i < 128 * 32; i += 256) w[i] = wt[i];
    for (int i = tid; i < 32; i += 256) w[128 * 32 + i] = b[i];
    __syncthreads();
    int v = blockIdx.x * 256 + tid;
    float acc[32];
#pragma unroll
    for (int co = 0; co < 32; co++) acc[co] = w[128 * 32 + co];
#pragma unroll 1
    for (int ci = 0; ci < 64; ci++) {
        float val = A[ci * NV + v];
        if (A2) val += A2[ci * NV + v];
#pragma unroll
        for (int co = 0; co < 32; co++) acc[co] = fmaf(w[ci * 32 + co], val, acc[co]);
    }
#pragma unroll 1
    for (int ci = 64; ci < 128; ci++) {
        float val = B[(ci - 64) * NV + v];
#pragma unroll
        for (int co = 0; co < 32; co++) acc[co] = fmaf(w[ci * 32 + co], val, acc[co]);
    }
#pragma unroll
    for (int co = 0; co < 32; co++) h[co * NV + v] = fmaxf(acc[co], 0.f);
}

// ------- dilated body conv 32->32, 3x3x3, dil D; writes c + GN sums --------
template <int D>
__global__ void __launch_bounds__(128) k_body(const float* __restrict__ hin,
                                              const float* __restrict__ wt,
                                              const float* __restrict__ b,
                                              float* __restrict__ cout) {
    extern __shared__ __align__(16) float patch[];
    constexpr int LEN = 16 + 2 * D;
    __shared__ float gsh[8], gqh[8];
    int tid = threadIdx.x;
    if (tid < 8) { gsh[tid] = 0.f; gqh[tid] = 0.f; }
    int p0 = blockIdx.x * 4;
    const int PER = 32 * 9 * LEN;
    for (int i = tid; i < 4 * PER; i += 128) {
        int lc = i / PER;
        int r = i - lc * PER;
        int ci = r / (9 * LEN);
        int r2 = r - ci * (9 * LEN);
        int dd = r2 / LEN;
        int ziz = r2 - dd * LEN;
        int p = p0 + lc;
        int x = p / Yd, y = p - x * Yd;
        int ix = x + D * (dd / 3 - 1), iy = y + D * (dd % 3 - 1), iz = ziz - D;
        float v = 0.f;
        if ((unsigned)ix < (unsigned)Xd && (unsigned)iy < (unsigned)Yd && (unsigned)iz < (unsigned)Zd)
            v = __ldg(&hin[ci * NV + (ix * Yd + iy) * Zd + iz]);
        patch[((lc * 32 + ci) * 9 + dd) * 24 + ziz] = v;
    }
    __syncthreads();
    int lc = tid >> 5, co = tid & 31;
    int p = p0 + lc;
    float bb = __ldg(&b[co]);
    float acc[16];
#pragma unroll
    for (int z = 0; z < 16; z++) acc[z] = bb;
    const float* pb = patch + lc * 32 * 9 * 24;
#pragma unroll 1
    for (int ci = 0; ci < 32; ci++) {
#pragma unroll
        for (int dd = 0; dd < 9; dd++) {
            const float* col = pb + (ci * 9 + dd) * 24;
            float v[LEN];
            const float4* c4 = reinterpret_cast<const float4*>(col);
#pragma unroll
            for (int q = 0; q < LEN / 4; q++) {
                float4 t = c4[q];
                v[4 * q] = t.x; v[4 * q + 1] = t.y; v[4 * q + 2] = t.z; v[4 * q + 3] = t.w;
            }
#pragma unroll
            for (int r = (LEN / 4) * 4; r < LEN; r++) v[r] = col[r];
            const float* wp = wt + (ci * 27 + dd * 3) * 32 + co;
#pragma unroll
            for (int kz = 0; kz < 3; kz++) {
                float ww = __ldg(&wp[kz * 32]);
#pragma unroll
                for (int z = 0; z < 16; z++) acc[z] = fmaf(v[z + kz * D], ww, acc[z]);
            }
        }
    }
    float s = 0.f, ss = 0.f;
    float* op = cout + co * NV + p * 16;
#pragma unroll
    for (int z = 0; z < 16; z++) {
        float o = acc[z];
        s += o; ss += o * o;
        op[z] = o;
    }
    atomicAdd(&gsh[co >> 2], s);
    atomicAdd(&gqh[co >> 2], ss);
    __syncthreads();
    if (tid < 8) {
        atomicAdd(&d_gsum[tid], gsh[tid]);
        atomicAdd(&d_gss[tid], gqh[tid]);
    }
}

__global__ void k_gnfin() {
    int g = threadIdx.x;
    if (g < 8) {
        float inv = 1.f / (4.f * (float)NV);
        float m = d_gsum[g] * inv;
        float var = d_gss[g] * inv - m * m;
        d_gmr[g] = m;
        d_gmr[8 + g] = rsqrtf(var + 1e-5f);
        d_gsum[g] = 0.f;
        d_gss[g] = 0.f;
    }
}

__global__ void k_gnapply(const float* __restrict__ cbuf, const float* __restrict__ sc,
                          const float* __restrict__ bi, float* __restrict__ h) {
    int c = blockIdx.y;
    int i = blockIdx.x * 256 + threadIdx.x;
    int g = c >> 2;
    float m = d_gmr[g], r = d_gmr[8 + g];
    float val = (cbuf[c * NV + i] - m) * r * __ldg(&sc[c]) + __ldg(&bi[c]);
    h[c * NV + i] += fmaxf(val, 0.f);
}

// -------- g_out: t = tanh(W(64x32)h+b)*dX; k1-mode or Heun-z-mode ----------
__global__ void __launch_bounds__(256) k_gout(const float* __restrict__ h, const float* __restrict__ wt,
                                              const float* __restrict__ b, const float* __restrict__ dX,
                                              float* __restrict__ k1out, const float* __restrict__ zw,
                                              const float* __restrict__ k1in, float* __restrict__ zout) {
    __shared__ float w[32 * 64 + 64];
    int tid = threadIdx.x;
    for (int i = tid; i < 32 * 64; i += 256) w[i] = wt[i];
    for (int i = tid; i < 64; i += 256) w[32 * 64 + i] = b[i];
    __syncthreads();
    int v = blockIdx.x * 256 + tid;
    float acc[64];
#pragma unroll
    for (int co = 0; co < 64; co++) acc[co] = w[32 * 64 + co];
#pragma unroll 1
    for (int ci = 0; ci < 32; ci++) {
        float val = h[ci * NV + v];
#pragma unroll
        for (int co = 0; co < 64; co++) acc[co] = fmaf(w[ci * 64 + co], val, acc[co]);
    }
#pragma unroll 1
    for (int co = 0; co < 64; co++) {
        int idx = co * NV + v;
        float t = tanhf(acc[co]) * dX[idx];
        if (zout)
            zout[idx] = zw[idx] + 0.5f * (k1in[idx] + t);
        else
            k1out[idx] = t;
    }
}

// ----- decoder: nearest x2 (XY) + conv 64->18 3x3x3 + fast_logits[3] -------
__global__ void __launch_bounds__(160) k_dec(const float* __restrict__ zf,
                                             const float* __restrict__ wt,
                                             const float* __restrict__ b,
                                             const float* __restrict__ flast,
                                             float* __restrict__ out) {
    extern __shared__ __align__(16) float patch[];
    int tid = threadIdx.x;
    int gx = blockIdx.x / 100, gy = blockIdx.x - gx * 100;
    int x0 = gx * 4, y0 = gy * 2;
    int dx0 = x0 / 2 - 1, dy0 = y0 / 2 - 1;
    for (int i = tid; i < 64 * 12 * 18; i += 160) {
        int ci = i / 216;
        int r = i - ci * 216;
        int dd = r / 18;
        int ziz = r - dd * 18;
        int ddx = dx0 + dd / 3, ddy = dy0 + dd % 3, iz = ziz - 1;
        float v = 0.f;
        if ((unsigned)ddx < (unsigned)Xd && (unsigned)ddy < (unsigned)Yd && (unsigned)iz < (unsigned)Zd)
            v = __ldg(&zf[ci * NV + (ddx * Yd + ddy) * Zd + iz]);
        patch[(ci * 12 + dd) * 20 + ziz] = v;
    }
    __syncthreads();
    if (tid >= 144) return;
    int col = tid / 18, co = tid - col * 18;
    int lx = col >> 1, ly = col & 1;
    int x = x0 + lx, y = y0 + ly;
    int pdx[3], pdy[3];
#pragma unroll
    for (int kk = 0; kk < 3; kk++) {
        int id = x + kk - 1;
        pdx[kk] = ((id < 0) ? -1 : (id >> 1)) - dx0;
        int jd = y + kk - 1;
        pdy[kk] = ((jd < 0) ? -1 : (jd >> 1)) - dy0;
    }
    float bb = __ldg(&b[co]);
    float acc[16];
#pragma unroll
    for (int z = 0; z < 16; z++) acc[z] = bb;
#pragma unroll 1
    for (int ci = 0; ci < 64; ci++) {
#pragma unroll
        for (int kx = 0; kx < 3; kx++) {
#pragma unroll
            for (int ky = 0; ky < 3; ky++) {
                const float* colp = patch + (ci * 12 + pdx[kx] * 3 + pdy[ky]) * 20;
                float v[18];
                const float4* c4 = reinterpret_cast<const float4*>(colp);
#pragma unroll
                for (int q = 0; q < 4; q++) {
                    float4 t = c4[q];
                    v[4 * q] = t.x; v[4 * q + 1] = t.y; v[4 * q + 2] = t.z; v[4 * q + 3] = t.w;
                }
                v[16] = colp[16]; v[17] = colp[17];
                const float* wp = wt + (ci * 27 + (kx * 3 + ky) * 3) * 18 + co;
#pragma unroll
                for (int kz = 0; kz < 3; kz++) {
                    float ww = __ldg(&wp[kz * 18]);
#pragma unroll
                    for (int z = 0; z < 16; z++) acc[z] = fmaf(v[z + kz], ww, acc[z]);
                }
            }
        }
    }
    int ob = co * NVF + (x * Y + y) * Z;
#pragma unroll
    for (int z = 0; z < 16; z++) out[ob + z] = acc[z] + __ldg(&flast[ob + z]);
}

// --------------------------------- host ------------------------------------
static float* sym_addr(const void* s) { void* p = nullptr; cudaGetSymbolAddress(&p, s); return (float*)p; }

extern "C" void kernel_launch(void* const* d_in, const int* in_sizes, int n_in,
                              void* d_out, int out_size) {
    (void)in_sizes; (void)n_in; (void)out_size;
    const float* fast_logits = (const float*)d_in[0];
    const float* slow_logits = (const float*)d_in[1];
    const float* pose   = (const float*)d_in[2];
    const float* fe_w   = (const float*)d_in[3];
    const float* fe_b   = (const float*)d_in[4];
    const float* se_w   = (const float*)d_in[5];
    const float* se_b   = (const float*)d_in[6];
    const float* ctrl_w = (const float*)d_in[7];
    const float* ctrl_b = (const float*)d_in[8];
    const float* gin_w  = (const float*)d_in[9];
    const float* gin_b  = (const float*)d_in[10];
    const float* gbw    = (const float*)d_in[11];
    const float* gbb    = (const float*)d_in[12];
    const float* gns    = (const float*)d_in[13];
    const float* gnb    = (const float*)d_in[14];
    const float* gout_w = (const float*)d_in[15];
    const float* gout_b = (const float*)d_in[16];
    const float* dec_w  = (const float*)d_in[17];
    const float* dec_b  = (const float*)d_in[18];
    const int*   ts     = (const int*)d_in[19];
    float* out = (float*)d_out;

    float* p_fast  = sym_addr(d_fast);
    float* p_z     = sym_addr(d_z);
    float* p_zw    = sym_addr(d_zw);
    float* p_fadv  = sym_addr(d_fadv);
    float* p_dX    = sym_addr(d_dX);
    float* p_k1    = sym_addr(d_k1);
    float* p_h     = sym_addr(d_h);
    float* p_c     = sym_addr(d_c);
    float* p_wfe   = sym_addr(d_wfe);
    float* p_wse   = sym_addr(d_wse);
    float* p_wbody = sym_addr(d_wbody);
    float* p_wdec  = sym_addr(d_wdec);
    float* p_wctrl = sym_addr(d_wctrl);
    float* p_wgin  = sym_addr(d_wgin);
    float* p_wgout = sym_addr(d_wgout);

    cudaFuncSetAttribute(k_body<1>, cudaFuncAttributeMaxDynamicSharedMemorySize, 110592);
    cudaFuncSetAttribute(k_body<2>, cudaFuncAttributeMaxDynamicSharedMemorySize, 110592);
    cudaFuncSetAttribute(k_body<3>, cudaFuncAttributeMaxDynamicSharedMemorySize, 110592);
    cudaFuncSetAttribute(k_dec, cudaFuncAttributeMaxDynamicSharedMemorySize, 61440);

    auto rp = [](const float* in, float* outp, int C, int J) {
        k_repack<<<(C * J + 255) / 256, 256>>>(in, outp, C, J);
    };
    rp(fe_w, p_wfe, 64, 486);
    rp(se_w, p_wse, 64, 486);
    for (int l = 0; l < 3; l++) rp(gbw + l * 27648, p_wbody + l * 27648, 32, 864);
    rp(dec_w, p_wdec, 18, 1728);
    rp(ctrl_w, p_wctrl, 64, 65);
    rp(gin_w, p_wgin, 32, 128);
    rp(gout_w, p_wgout, 64, 32);
    k_transforms<<<1, 1>>>(pose, ts);

    for (int t = 0; t < 4; t++)
        k_enc<<<NCOLS / 2, 128>>>(fast_logits + (size_t)t * CL * NVF, p_wfe, fe_b,
                                  p_fast + (size_t)t * 64 * NV);
    k_enc<<<NCOLS / 2, 128>>>(slow_logits, p_wse, se_b, p_z);
    k_sub<<<(64 * NV + 255) / 256, 256>>>(p_z, p_fast, 64 * NV);

    for (int k = 0; k < 3; k++) {
        const float* fk  = p_fast + (size_t)k * 64 * NV;
        const float* fk1 = p_fast + (size_t)(k + 1) * 64 * NV;
        k_warp<<<NV / 256, 256>>>(p_z, fk, p_zw, p_fadv, k);
        k_ctrl<<<NV / 256, 256>>>(fk1, p_fadv, p_wctrl, ctrl_b, p_dX, k);
        for (int pass = 0; pass < 2; pass++) {
            if (pass == 0)
                k_gin<<<NV / 256, 256>>>(p_zw, nullptr, p_fadv, p_wgin, gin_b, p_h);
            else
                k_gin<<<NV / 256, 256>>>(p_zw, p_k1, fk1, p_wgin, gin_b, p_h);
            for (int l = 0; l < 3; l++) {
                if (l == 0)
                    k_body<1><<<NCOLS / 4, 128, 110592>>>(p_h, p_wbody, gbb, p_c);
                else if (l == 1)
                    k_body<2><<<NCOLS / 4, 128, 110592>>>(p_h, p_wbody + 27648, gbb + 32, p_c);
                else
                    k_body<3><<<NCOLS / 4, 128, 110592>>>(p_h, p_wbody + 2 * 27648, gbb + 64, p_c);
                k_gnfin<<<1, 8>>>();
                k_gnapply<<<dim3(NV / 256, 32), 256>>>(p_c, gns + l * 32, gnb + l * 32, p_h);
            }
            if (pass == 0)
                k_gout<<<NV / 256, 256>>>(p_h, p_wgout, gout_b, p_dX, p_k1,
                                          nullptr, nullptr, nullptr);
            else
                k_gout<<<NV / 256, 256>>>(p_h, p_wgout, gout_b, p_dX, nullptr,
                                          p_zw, p_k1, p_z);
        }
    }
    k_dec<<<5000, 160, 61440>>>(p_z, p_wdec, dec_b, fast_logits + (size_t)3 * CL * NVF, out);
}